// round 4
// baseline (speedup 1.0000x reference)
#include <cuda_runtime.h>
#include <math.h>

// Problem-fixed sizes (inputs are a fixed dataset; runtime values derived from
// in_sizes fit these statics by construction).
#define NNODE 50000
#define EEDGE 200000
#define ESMAX (EEDGE + NNODE)
#define RNUM 65
#define HDIM 256
#define GNUM 1600
#define MDIM 64
#define MAXTILES 4096

// ---------------- device scratch (allocation-free rule: __device__ globals) ----
__device__ int   g_flag64[3];               // 1 if buffer is int64, else int32
__device__ int   g_esrc[EEDGE];
__device__ int   g_edst[EEDGE];
__device__ int   g_etype[EEDGE];
__device__ int   g_batch[NNODE];
__device__ float g_cnt[NNODE * RNUM];       // counts, then inverted in place
__device__ int   g_hist[RNUM];
__device__ int   g_cursor[RNUM];
__device__ int   g_ts[MAXTILES];
__device__ int   g_tc[MAXTILES];
__device__ int   g_tr[MAXTILES];
__device__ int   g_ntiles;
__device__ int   g_src[ESMAX];
__device__ int   g_dst[ESMAX];
__device__ float g_h1[(size_t)NNODE * HDIM];
__device__ float g_h2[(size_t)NNODE * HDIM];
__device__ float g_emb[GNUM * HDIM];

// ---------------- f32x2 helpers (packed dual-fp32 FMA; ptxas never emits these
// from C++ — PTX-only path, see SASS patterns notes) -----------------------------
__device__ __forceinline__ unsigned long long pack2(float x)
{
    unsigned long long r;
    unsigned int u = __float_as_uint(x);
    asm("mov.b64 %0, {%1, %1};" : "=l"(r) : "r"(u));
    return r;
}
__device__ __forceinline__ void fma2(unsigned long long& d,
                                     unsigned long long a, unsigned long long b)
{
    asm("fma.rn.f32x2 %0, %1, %2, %3;" : "=l"(d) : "l"(a), "l"(b), "l"(d));
}
__device__ __forceinline__ float2 unpack2(unsigned long long v)
{
    unsigned int lo, hi;
    asm("mov.b64 {%0, %1}, %2;" : "=r"(lo), "=r"(hi) : "l"(v));
    return make_float2(__uint_as_float(lo), __uint_as_float(hi));
}

// ---------------- dtype detection (int32 vs int64 index buffers) --------------
// For little-endian int64 buffers holding values < 2^31, every odd 32-bit word
// is zero. Sample 256 odd words, bounded so we never read OOB under either
// interpretation (n is the element count; int32 view has >= n words).
__global__ void k_detect(const void* p0, int n0, const void* p1, int n1,
                         const void* p2, int n2)
{
    const unsigned int* p;
    int n;
    int b = blockIdx.x;
    if (b == 0)      { p = (const unsigned int*)p0; n = n0; }
    else if (b == 1) { p = (const unsigned int*)p1; n = n1; }
    else             { p = (const unsigned int*)p2; n = n2; }
    __shared__ int s_nz;
    if (threadIdx.x == 0) s_nz = 0;
    __syncthreads();
    int kmax = (n - 1) >> 1;
    if (kmax > 0) {
        int k = (int)(((long long)threadIdx.x * kmax) >> 8);
        if (p[2 * k + 1] != 0u) s_nz = 1;
    }
    __syncthreads();
    if (threadIdx.x == 0) g_flag64[b] = s_nz ? 0 : 1;
}

__global__ void k_convert_edges(const void* eidx, const void* ety, int E)
{
    int i = blockIdx.x * blockDim.x + threadIdx.x;
    if (i >= E) return;
    if (g_flag64[0]) {
        const long long* p = (const long long*)eidx;
        g_esrc[i] = (int)p[i];
        g_edst[i] = (int)p[E + i];
    } else {
        const int* p = (const int*)eidx;
        g_esrc[i] = p[i];
        g_edst[i] = p[E + i];
    }
    g_etype[i] = g_flag64[1] ? (int)((const long long*)ety)[i]
                             : ((const int*)ety)[i];
}

__global__ void k_convert_batch(const void* batch, int N)
{
    int i = blockIdx.x * blockDim.x + threadIdx.x;
    if (i >= N) return;
    g_batch[i] = g_flag64[2] ? (int)((const long long*)batch)[i]
                             : ((const int*)batch)[i];
}

// ---------------- fused zero: g_cnt, g_hist, g_emb -----------------------------
__global__ void k_zero_all(int ncnt, int nemb)
{
    int i = blockIdx.x * blockDim.x + threadIdx.x;
    if (i < ncnt) g_cnt[i] = 0.f;
    if (i < nemb) g_emb[i] = 0.f;
    if (i < RNUM) g_hist[i] = 0;
}

// ---------------- fused count: per-(dst,rel) counts + relation histogram ------
__global__ void k_count(int E, int N)
{
    int i = blockIdx.x * blockDim.x + threadIdx.x;
    if (i < E) {
        int r = g_etype[i];
        atomicAdd(&g_cnt[g_edst[i] * RNUM + r], 1.f);
        atomicAdd(&g_hist[r], 1);
    } else if (i < E + N) {
        atomicAdd(&g_cnt[(i - E) * RNUM], 1.f);  // self loop, relation 0
    }
}

__global__ void k_invert(int n)
{
    int i = blockIdx.x * blockDim.x + threadIdx.x;
    if (i < n) g_cnt[i] = 1.f / fmaxf(g_cnt[i], 1.f);
}

__global__ void k_scan_tiles(int N)
{
    if (blockIdx.x != 0 || threadIdx.x != 0) return;
    int off = 0, nt = 0;
    for (int r = 0; r < RNUM; r++) {
        int c = g_hist[r] + (r == 0 ? N : 0);  // relation 0 gains N self loops
        g_cursor[r] = off;
        for (int s = 0; s < c; s += 128) {
            g_ts[nt] = off + s;
            g_tc[nt] = (c - s < 128) ? (c - s) : 128;
            g_tr[nt] = r;
            nt++;
        }
        off += c;
    }
    g_ntiles = nt;
}

__global__ void k_scatter(int E, int N)
{
    int i = blockIdx.x * blockDim.x + threadIdx.x;
    if (i < E) {
        int r = g_etype[i];
        int p = atomicAdd(&g_cursor[r], 1);
        g_src[p] = g_esrc[i];
        g_dst[p] = g_edst[i];
    } else if (i < E + N) {
        int v = i - E;
        int p = atomicAdd(&g_cursor[0], 1);
        g_src[p] = v;
        g_dst[p] = v;
    }
}

// ---------------- dense root GEMM: out = bias + X @ Wr ------------------------
// 128x128 block tile, 8x8 microtile (f32x2-packed along j), K-tile 8, 256 thr.
__global__ __launch_bounds__(256) void k_dense(
    const float* __restrict__ X, const float* __restrict__ Wr,
    const float* __restrict__ bias, float* __restrict__ out, int N, int D)
{
    __shared__ __align__(16) float As[8][132];   // padded, transposed stores
    __shared__ __align__(16) float Bs[8][128];

    int mbase = blockIdx.x * 128;
    int nbase = blockIdx.y * 128;
    int tid = threadIdx.x;
    int tm = tid & 15, tn = tid >> 4;
    int lm = tid >> 1, lkq = (tid & 1) * 4;    // A-load mapping
    int kk = tid >> 5, nn = (tid & 31) * 4;    // B-load mapping

    int rowA = mbase + lm;
    if (rowA >= N) rowA = N - 1;

    unsigned long long acc2[8][4];
#pragma unroll
    for (int i = 0; i < 8; i++)
#pragma unroll
        for (int j = 0; j < 4; j++) acc2[i][j] = 0ull;

    for (int kb = 0; kb < D; kb += 8) {
        float4 a4 = *(const float4*)&X[(size_t)rowA * D + kb + lkq];
        As[lkq + 0][lm] = a4.x;
        As[lkq + 1][lm] = a4.y;
        As[lkq + 2][lm] = a4.z;
        As[lkq + 3][lm] = a4.w;
        float4 b4 = *(const float4*)&Wr[(size_t)(kb + kk) * HDIM + nbase + nn];
        *(float4*)&Bs[kk][nn] = b4;
        __syncthreads();
#pragma unroll
        for (int k = 0; k < 8; k++) {
            float a[8];
            *(float4*)&a[0] = *(const float4*)&As[k][tm * 8];
            *(float4*)&a[4] = *(const float4*)&As[k][tm * 8 + 4];
            ulonglong2 b01 = *(const ulonglong2*)&Bs[k][tn * 8];
            ulonglong2 b23 = *(const ulonglong2*)&Bs[k][tn * 8 + 4];
            unsigned long long bb0 = b01.x, bb1 = b01.y, bb2 = b23.x, bb3 = b23.y;
#pragma unroll
            for (int i = 0; i < 8; i++) {
                unsigned long long ap = pack2(a[i]);
                fma2(acc2[i][0], ap, bb0);
                fma2(acc2[i][1], ap, bb1);
                fma2(acc2[i][2], ap, bb2);
                fma2(acc2[i][3], ap, bb3);
            }
        }
        __syncthreads();
    }

#pragma unroll
    for (int i = 0; i < 8; i++) {
        int row = mbase + tm * 8 + i;
        if (row < N) {
            float* op = &out[(size_t)row * HDIM + nbase + tn * 8];
            const float* bp = &bias[nbase + tn * 8];
#pragma unroll
            for (int j = 0; j < 4; j++) {
                float2 v = unpack2(acc2[i][j]);
                op[2 * j + 0] = bp[2 * j + 0] + v.x;
                op[2 * j + 1] = bp[2 * j + 1] + v.y;
            }
        }
    }
}

// ---------------- relation-blocked edge GEMM + scatter -------------------------
// One block = (tile of <=128 edges of one relation) x (128 output cols).
// A row m = invcnt[dst_m, rel] * X[src_m, :]; B = W[rel]; atomicAdd into out[dst].
__global__ __launch_bounds__(256) void k_edge(
    const float* __restrict__ X, const float* __restrict__ Wall,
    float* __restrict__ out, int D)
{
    int t = blockIdx.x;
    if (t >= g_ntiles) return;
    int start = g_ts[t], cnt = g_tc[t], rel = g_tr[t];
    int nbase = blockIdx.y * 128;
    const float* Wr = Wall + (size_t)rel * D * HDIM;

    __shared__ __align__(16) float As[8][132];
    __shared__ __align__(16) float Bs[8][128];
    __shared__ int   s_srcv[128];
    __shared__ int   s_dst[128];
    __shared__ float s_inv[128];

    int tid = threadIdx.x;
    if (tid < 128) {
        int m = tid;
        if (m < cnt) {
            int e = start + m;
            int sv = g_src[e], dv = g_dst[e];
            s_srcv[m] = sv;
            s_dst[m]  = dv;
            s_inv[m]  = g_cnt[dv * RNUM + rel];   // inverted counts
        } else {
            s_srcv[m] = g_src[start];
            s_dst[m]  = -1;
            s_inv[m]  = 0.f;
        }
    }
    __syncthreads();

    int tm = tid & 15, tn = tid >> 4;
    int lm = tid >> 1, lkq = (tid & 1) * 4;
    int kk = tid >> 5, nn = (tid & 31) * 4;
    int rowA = s_srcv[lm];
    float sc = s_inv[lm];

    unsigned long long acc2[8][4];
#pragma unroll
    for (int i = 0; i < 8; i++)
#pragma unroll
        for (int j = 0; j < 4; j++) acc2[i][j] = 0ull;

    for (int kb = 0; kb < D; kb += 8) {
        float4 a4 = *(const float4*)&X[(size_t)rowA * D + kb + lkq];
        As[lkq + 0][lm] = a4.x * sc;
        As[lkq + 1][lm] = a4.y * sc;
        As[lkq + 2][lm] = a4.z * sc;
        As[lkq + 3][lm] = a4.w * sc;
        float4 b4 = *(const float4*)&Wr[(size_t)(kb + kk) * HDIM + nbase + nn];
        *(float4*)&Bs[kk][nn] = b4;
        __syncthreads();
#pragma unroll
        for (int k = 0; k < 8; k++) {
            float a[8];
            *(float4*)&a[0] = *(const float4*)&As[k][tm * 8];
            *(float4*)&a[4] = *(const float4*)&As[k][tm * 8 + 4];
            ulonglong2 b01 = *(const ulonglong2*)&Bs[k][tn * 8];
            ulonglong2 b23 = *(const ulonglong2*)&Bs[k][tn * 8 + 4];
            unsigned long long bb0 = b01.x, bb1 = b01.y, bb2 = b23.x, bb3 = b23.y;
#pragma unroll
            for (int i = 0; i < 8; i++) {
                unsigned long long ap = pack2(a[i]);
                fma2(acc2[i][0], ap, bb0);
                fma2(acc2[i][1], ap, bb1);
                fma2(acc2[i][2], ap, bb2);
                fma2(acc2[i][3], ap, bb3);
            }
        }
        __syncthreads();
    }

#pragma unroll
    for (int i = 0; i < 8; i++) {
        int m = tm * 8 + i;
        int dv = s_dst[m];
        if (dv >= 0) {
            float* op = &out[(size_t)dv * HDIM + nbase + tn * 8];
#pragma unroll
            for (int j = 0; j < 4; j++) {
                float2 v = unpack2(acc2[i][j]);
                atomicAdd(&op[2 * j + 0], v.x);
                atomicAdd(&op[2 * j + 1], v.y);
            }
        }
    }
}

__global__ void k_relu(float* p, int n)
{
    int i = blockIdx.x * blockDim.x + threadIdx.x;
    if (i < n) p[i] = fmaxf(p[i], 0.f);
}

// ---------------- pooling (with fused ReLU on h2) ------------------------------
// emb[batch[i]] += sigmoid(relu(h_i) . ws + wsb) * relu(h_i)
__global__ void k_pool(const float* __restrict__ h, const float* __restrict__ wsw,
                       const float* __restrict__ wsb, int N)
{
    int gtid = blockIdx.x * blockDim.x + threadIdx.x;
    int node = gtid >> 5;
    int lane = gtid & 31;
    if (node >= N) return;
    const float* hr = h + (size_t)node * HDIM;
    float hv[8];
    float dot = 0.f;
#pragma unroll
    for (int q = 0; q < 8; q++) {
        hv[q] = fmaxf(hr[lane + 32 * q], 0.f);   // fused ReLU
        dot += hv[q] * wsw[lane + 32 * q];
    }
#pragma unroll
    for (int o = 16; o > 0; o >>= 1) dot += __shfl_xor_sync(0xFFFFFFFFu, dot, o);
    float w = 1.f / (1.f + expf(-(dot + wsb[0])));
    float* er = g_emb + (size_t)g_batch[node] * HDIM;
#pragma unroll
    for (int q = 0; q < 8; q++) atomicAdd(&er[lane + 32 * q], w * hv[q]);
}

// ---------------- fused MLP head: one block per graph -------------------------
__global__ void k_mlp(const float* __restrict__ m1w, const float* __restrict__ m1b,
                      const float* __restrict__ m2w, const float* __restrict__ m2b,
                      const float* __restrict__ m3w, const float* __restrict__ m3b,
                      const float* __restrict__ ow,  const float* __restrict__ ob,
                      float* __restrict__ out)
{
    __shared__ float se[HDIM];
    __shared__ float s1[MDIM];
    __shared__ float s2[MDIM];
    __shared__ float sr[MDIM];
    int g = blockIdx.x;
    int t = threadIdx.x;   // 64 threads
    for (int k = t; k < HDIM; k += MDIM) se[k] = g_emb[(size_t)g * HDIM + k];
    __syncthreads();
    float a = m1b[t];
    for (int k = 0; k < HDIM; k++) a += se[k] * m1w[k * MDIM + t];
    s1[t] = fmaxf(a, 0.f);
    __syncthreads();
    float b = m2b[t];
    for (int k = 0; k < MDIM; k++) b += s1[k] * m2w[k * MDIM + t];
    s2[t] = fmaxf(b, 0.f);
    __syncthreads();
    float c = m3b[t];
    for (int k = 0; k < MDIM; k++) c += s2[k] * m3w[k * MDIM + t];
    sr[t] = c * ow[t];
    __syncthreads();
    for (int o = 32; o > 0; o >>= 1) {
        if (t < o) sr[t] += sr[t + o];
        __syncthreads();
    }
    if (t == 0) out[g] = sr[0] + ob[0];
}

// ---------------- host side ----------------------------------------------------
extern "C" void kernel_launch(void* const* d_in, const int* in_sizes, int n_in,
                              void* d_out, int out_size)
{
    const float* x     = (const float*)d_in[0];
    const void*  eidx  = d_in[1];
    const void*  ety   = d_in[2];
    const void*  batch = d_in[3];
    const float* W1    = (const float*)d_in[4];
    const float* root1 = (const float*)d_in[5];
    const float* b1    = (const float*)d_in[6];
    const float* W2    = (const float*)d_in[7];
    const float* root2 = (const float*)d_in[8];
    const float* b2    = (const float*)d_in[9];
    const float* wsw   = (const float*)d_in[10];
    const float* wsb   = (const float*)d_in[11];
    const float* m1w   = (const float*)d_in[12];
    const float* m1b   = (const float*)d_in[13];
    const float* m2w   = (const float*)d_in[14];
    const float* m2b   = (const float*)d_in[15];
    const float* m3w   = (const float*)d_in[16];
    const float* m3b   = (const float*)d_in[17];
    const float* ow    = (const float*)d_in[18];
    const float* ob    = (const float*)d_in[19];
    float* out = (float*)d_out;

    int H = in_sizes[6];            // 256
    int F = in_sizes[5] / H;        // 128
    int N = in_sizes[0] / F;        // 50000
    int E = in_sizes[2];            // 200000
    int G = out_size;               // 1600

    float *p_h1 = nullptr, *p_h2 = nullptr;
    cudaGetSymbolAddress((void**)&p_h1, g_h1);
    cudaGetSymbolAddress((void**)&p_h2, g_h2);

    // --- index normalization + per-(node,relation) inverse counts ---
    k_detect<<<3, 256>>>(eidx, 2 * E, ety, E, batch, N);
    k_convert_edges<<<(E + 255) / 256, 256>>>(eidx, ety, E);
    k_convert_batch<<<(N + 255) / 256, 256>>>(batch, N);

    int ncnt = N * RNUM;
    k_zero_all<<<(ncnt + 255) / 256, 256>>>(ncnt, G * H);
    k_count<<<(E + N + 255) / 256, 256>>>(E, N);
    k_invert<<<(ncnt + 255) / 256, 256>>>(ncnt);

    // --- counting sort of (edges + self loops) by relation, tile build ---
    k_scan_tiles<<<1, 1>>>(N);
    k_scatter<<<(E + N + 255) / 256, 256>>>(E, N);

    int ubTiles = (E + N + 127) / 128 + RNUM + 1;
    dim3 edgeGrid(ubTiles, H / 128);
    int nh = N * H;

    // --- layer 1: h1 = relu(b1 + X@root1 + edge aggregation with W1) ---
    k_dense<<<dim3((N + 127) / 128, H / 128), 256>>>(x, root1, b1, p_h1, N, F);
    k_edge<<<edgeGrid, 256>>>(x, W1, p_h1, F);
    k_relu<<<(nh + 255) / 256, 256>>>(p_h1, nh);

    // --- layer 2: h2 = b2 + h1@root2 + edge aggregation with W2 (ReLU in pool) ---
    k_dense<<<dim3((N + 127) / 128, H / 128), 256>>>(p_h1, root2, b2, p_h2, N, H);
    k_edge<<<edgeGrid, 256>>>(p_h1, W2, p_h2, H);

    // --- weighted-sum pooling (applies ReLU to h2 on the fly) ---
    k_pool<<<(N + 7) / 8, 256>>>(p_h2, wsw, wsb, N);

    // --- MLP head ---
    k_mlp<<<G, MDIM>>>(m1w, m1b, m2w, m2b, m3w, m3b, ow, ob, out);
}

// round 8
// speedup vs baseline: 1.0696x; 1.0696x over previous
#include <cuda_runtime.h>
#include <cuda_bf16.h>
#include <math.h>
#include <stdint.h>

// Problem-fixed sizes.
#define NNODE 50000
#define EEDGE 200000
#define ESMAX (EEDGE + NNODE)
#define RNUM 65
#define FDIM 128
#define HDIM 256
#define GNUM 1600
#define MDIM 64
#define MAXTILES 4096

// ---------------- device scratch (allocation-free rule: __device__ globals) ----
__device__ int   g_flag64[3];
__device__ int   g_esrc[EEDGE];
__device__ int   g_edst[EEDGE];
__device__ int   g_etype[EEDGE];
__device__ int   g_batch[NNODE];
__device__ float g_cnt[NNODE * RNUM];
__device__ int   g_hist[RNUM];
__device__ int   g_cursor[RNUM];
__device__ int   g_ts[MAXTILES];
__device__ int   g_tc[MAXTILES];
__device__ int   g_tr[MAXTILES];
__device__ int   g_ntiles;
__device__ int   g_src[ESMAX];
__device__ int   g_dst[ESMAX];
__device__ float g_h1[(size_t)NNODE * HDIM];
__device__ float g_h2[(size_t)NNODE * HDIM];
__device__ float g_emb[GNUM * HDIM];

// bf16 hi/lo split buffers (Dekker split: x = hi + lo)
__device__ __align__(16) unsigned short g_xhi[(size_t)NNODE * FDIM];
__device__ __align__(16) unsigned short g_xlo[(size_t)NNODE * FDIM];
__device__ __align__(16) unsigned short g_h1hi[(size_t)NNODE * HDIM];
__device__ __align__(16) unsigned short g_h1lo[(size_t)NNODE * HDIM];
// transposed weights: [r][n(256)][k]  (K-major rows = "col" operand for mma)
__device__ __align__(16) unsigned short g_w1thi[(size_t)RNUM * HDIM * FDIM];
__device__ __align__(16) unsigned short g_w1tlo[(size_t)RNUM * HDIM * FDIM];
__device__ __align__(16) unsigned short g_w2thi[(size_t)RNUM * HDIM * HDIM];
__device__ __align__(16) unsigned short g_w2tlo[(size_t)RNUM * HDIM * HDIM];
__device__ __align__(16) unsigned short g_rt1hi[HDIM * FDIM];
__device__ __align__(16) unsigned short g_rt1lo[HDIM * FDIM];
__device__ __align__(16) unsigned short g_rt2hi[HDIM * HDIM];
__device__ __align__(16) unsigned short g_rt2lo[HDIM * HDIM];

// ---------------- PTX helpers (sm_80-era features only: compile for compute_103)
__device__ __forceinline__ uint32_t smem_u32(const void* p)
{
    uint32_t a;
    asm("{ .reg .u64 t; cvta.to.shared.u64 t, %1; cvt.u32.u64 %0, t; }"
        : "=r"(a) : "l"(p));
    return a;
}

__device__ __forceinline__ void ldm_x4(uint32_t* r, uint32_t addr)
{
    asm volatile("ldmatrix.sync.aligned.m8n8.x4.shared.b16 {%0,%1,%2,%3}, [%4];"
                 : "=r"(r[0]), "=r"(r[1]), "=r"(r[2]), "=r"(r[3]) : "r"(addr));
}

__device__ __forceinline__ void mma_bf16(float* c, const uint32_t* a, const uint32_t* b)
{
    asm volatile(
        "mma.sync.aligned.m16n8k16.row.col.f32.bf16.bf16.f32 "
        "{%0,%1,%2,%3}, {%4,%5,%6,%7}, {%8,%9}, {%0,%1,%2,%3};"
        : "+f"(c[0]), "+f"(c[1]), "+f"(c[2]), "+f"(c[3])
        : "r"(a[0]), "r"(a[1]), "r"(a[2]), "r"(a[3]), "r"(b[0]), "r"(b[1]));
}

// ---------------- setup kernels -------------------------------------------------
__global__ void k_detect(const void* p0, int n0, const void* p1, int n1,
                         const void* p2, int n2)
{
    const unsigned int* p;
    int n;
    int b = blockIdx.x;
    if (b == 0)      { p = (const unsigned int*)p0; n = n0; }
    else if (b == 1) { p = (const unsigned int*)p1; n = n1; }
    else             { p = (const unsigned int*)p2; n = n2; }
    __shared__ int s_nz;
    if (threadIdx.x == 0) s_nz = 0;
    __syncthreads();
    int kmax = (n - 1) >> 1;
    if (kmax > 0) {
        int k = (int)(((long long)threadIdx.x * kmax) >> 8);
        if (p[2 * k + 1] != 0u) s_nz = 1;
    }
    __syncthreads();
    if (threadIdx.x == 0) g_flag64[b] = s_nz ? 0 : 1;
}

__global__ void k_convert_edges(const void* eidx, const void* ety, int E)
{
    int i = blockIdx.x * blockDim.x + threadIdx.x;
    if (i >= E) return;
    if (g_flag64[0]) {
        const long long* p = (const long long*)eidx;
        g_esrc[i] = (int)p[i];
        g_edst[i] = (int)p[E + i];
    } else {
        const int* p = (const int*)eidx;
        g_esrc[i] = p[i];
        g_edst[i] = p[E + i];
    }
    g_etype[i] = g_flag64[1] ? (int)((const long long*)ety)[i]
                             : ((const int*)ety)[i];
}

__global__ void k_convert_batch(const void* batch, int N)
{
    int i = blockIdx.x * blockDim.x + threadIdx.x;
    if (i >= N) return;
    g_batch[i] = g_flag64[2] ? (int)((const long long*)batch)[i]
                             : ((const int*)batch)[i];
}

__global__ void k_zero_all(int ncnt, int nemb)
{
    int i = blockIdx.x * blockDim.x + threadIdx.x;
    if (i < ncnt) g_cnt[i] = 0.f;
    if (i < nemb) g_emb[i] = 0.f;
    if (i < RNUM) g_hist[i] = 0;
}

__global__ void k_count(int E, int N)
{
    int i = blockIdx.x * blockDim.x + threadIdx.x;
    if (i < E) {
        int r = g_etype[i];
        atomicAdd(&g_cnt[g_edst[i] * RNUM + r], 1.f);
        atomicAdd(&g_hist[r], 1);
    } else if (i < E + N) {
        atomicAdd(&g_cnt[(i - E) * RNUM], 1.f);  // self loop, relation 0
    }
}

__global__ void k_invert(int n)
{
    int i = blockIdx.x * blockDim.x + threadIdx.x;
    if (i < n) g_cnt[i] = 1.f / fmaxf(g_cnt[i], 1.f);
}

__global__ void k_scan_tiles(int N)
{
    if (blockIdx.x != 0 || threadIdx.x != 0) return;
    int off = 0, nt = 0;
    for (int r = 0; r < RNUM; r++) {
        int c = g_hist[r] + (r == 0 ? N : 0);
        g_cursor[r] = off;
        for (int s = 0; s < c; s += 128) {
            g_ts[nt] = off + s;
            g_tc[nt] = (c - s < 128) ? (c - s) : 128;
            g_tr[nt] = r;
            nt++;
        }
        off += c;
    }
    g_ntiles = nt;
}

__global__ void k_scatter(int E, int N)
{
    int i = blockIdx.x * blockDim.x + threadIdx.x;
    if (i < E) {
        int r = g_etype[i];
        int p = atomicAdd(&g_cursor[r], 1);
        g_src[p] = g_esrc[i];
        g_dst[p] = g_edst[i];
    } else if (i < E + N) {
        int v = i - E;
        int p = atomicAdd(&g_cursor[0], 1);
        g_src[p] = v;
        g_dst[p] = v;
    }
}

// ---------------- bf16 split conversions ---------------------------------------
__global__ void k_split(const float* __restrict__ src, unsigned short* __restrict__ hi,
                        unsigned short* __restrict__ lo, int n, int do_relu)
{
    int i = blockIdx.x * blockDim.x + threadIdx.x;
    if (i >= n) return;
    float v = src[i];
    if (do_relu) v = fmaxf(v, 0.f);
    __nv_bfloat16 h = __float2bfloat16(v);
    float r = v - __bfloat162float(h);
    __nv_bfloat16 l = __float2bfloat16(r);
    hi[i] = *(unsigned short*)&h;
    lo[i] = *(unsigned short*)&l;
}

// W: [R][K][256] -> out: [R][256][K], split
__global__ void k_split_t(const float* __restrict__ W, unsigned short* __restrict__ hi,
                          unsigned short* __restrict__ lo, int R, int K)
{
    int i = blockIdx.x * blockDim.x + threadIdx.x;
    int tot = R * K * 256;
    if (i >= tot) return;
    int n = i & 255;
    int k = (i >> 8) % K;
    int r = i / (K * 256);
    float v = W[i];
    __nv_bfloat16 h = __float2bfloat16(v);
    float rr = v - __bfloat162float(h);
    __nv_bfloat16 l = __float2bfloat16(rr);
    size_t o = ((size_t)r * 256 + n) * K + k;
    hi[o] = *(unsigned short*)&h;
    lo[o] = *(unsigned short*)&l;
}

// ---------------- HMMA GEMM: dense (mode 0) / edge gather-scatter (mode 1) -----
// Block tile: 128 rows x 128 cols (grid.y selects 128-col half of HDIM=256).
// 8 warps = 4 (m) x 2 (n); warp tile 32 x 64. K staged 64-wide in SMEM.
// D = Ahi*Bhi + Ahi*Blo + Alo*Bhi via mma.sync m16n8k16 bf16 (Dekker split).
// SMEM rows are 72 bf16 = 144 B: 8 ldmatrix row-addrs hit 8 distinct 16B
// groups mod 128 -> conflict-free without swizzle.
#define SM_SRC  0
#define SM_DST  512
#define SM_INV  1024
#define SM_A_HI 2048
#define SM_A_LO (SM_A_HI + 18432)
#define SM_B_HI (SM_A_LO + 18432)
#define SM_B_LO (SM_B_HI + 18432)
#define SMEM_BYTES (SM_B_LO + 18432)   // 75776
#define ROWB 144                        // smem row stride in bytes

__global__ __launch_bounds__(256) void k_mma(
    const unsigned short* __restrict__ Ahi, const unsigned short* __restrict__ Alo,
    const unsigned short* __restrict__ Bhi_all, const unsigned short* __restrict__ Blo_all,
    const float* __restrict__ bias, float* __restrict__ out,
    int K, int mode, int Nrows)
{
    extern __shared__ char smem[];
    uint32_t sb = smem_u32(smem);
    int tid = threadIdx.x;
    int wid = tid >> 5;
    int lane = tid & 31;
    int nbg = blockIdx.y * 128;   // global col base of this block

    int mbase = 0;
    const unsigned short *Bhi, *Blo;
    if (mode == 0) {
        mbase = blockIdx.x * 128;
        Bhi = Bhi_all + (size_t)nbg * K;
        Blo = Blo_all + (size_t)nbg * K;
        if (tid < 128) {
            int grow = mbase + tid;
            if (grow >= Nrows) grow = Nrows - 1;
            ((int*)(smem + SM_SRC))[tid] = grow;
        }
    } else {
        int t = blockIdx.x;
        if (t >= g_ntiles) return;
        int start = g_ts[t], cnt = g_tc[t], rel = g_tr[t];
        Bhi = Bhi_all + ((size_t)rel * 256 + nbg) * K;
        Blo = Blo_all + ((size_t)rel * 256 + nbg) * K;
        if (tid < 128) {
            if (tid < cnt) {
                int e = start + tid;
                int dv = g_dst[e];
                ((int*)(smem + SM_SRC))[tid] = g_src[e];
                ((int*)(smem + SM_DST))[tid] = dv;
                ((float*)(smem + SM_INV))[tid] = g_cnt[dv * RNUM + rel];
            } else {
                ((int*)(smem + SM_SRC))[tid] = g_src[start];
                ((int*)(smem + SM_DST))[tid] = -1;
                ((float*)(smem + SM_INV))[tid] = 0.f;
            }
        }
    }
    __syncthreads();
    const int* s_src = (const int*)(smem + SM_SRC);

    int wm = wid & 3, wn = wid >> 2;
    // ldmatrix per-lane address components
    int a_row = lane & 15;
    int a_k   = (lane >> 4) * 8;
    int b_row = ((lane >> 4) * 8) + (lane & 7);
    int b_k   = ((lane >> 3) & 1) * 8;

    float acc[2][8][4];
#pragma unroll
    for (int i = 0; i < 2; i++)
#pragma unroll
        for (int j = 0; j < 8; j++)
#pragma unroll
            for (int q = 0; q < 4; q++) acc[i][j][q] = 0.f;

    for (int kb = 0; kb < K; kb += 64) {
        // stage A(hi/lo) gathered rows + B(hi/lo) 128 rows, 64 cols each
        for (int u = tid; u < 4096; u += 256) {
            int buf = u >> 10;           // 0 Ahi, 1 Alo, 2 Bhi, 3 Blo
            int v = u & 1023;
            int row = v >> 3, seg = v & 7;
            const unsigned short* gp;
            if (buf == 0)      gp = Ahi + (size_t)s_src[row] * K;
            else if (buf == 1) gp = Alo + (size_t)s_src[row] * K;
            else if (buf == 2) gp = Bhi + (size_t)row * K;
            else               gp = Blo + (size_t)row * K;
            uint4 val = *(const uint4*)(gp + kb + seg * 8);
            int base = (buf == 0) ? SM_A_HI : (buf == 1) ? SM_A_LO
                     : (buf == 2) ? SM_B_HI : SM_B_LO;
            *(uint4*)(smem + base + row * ROWB + seg * 16) = val;
        }
        __syncthreads();

#pragma unroll
        for (int ks = 0; ks < 64; ks += 16) {
            uint32_t aH[2][4], aL[2][4];
#pragma unroll
            for (int i = 0; i < 2; i++) {
                uint32_t ra = (32 * wm + 16 * i + a_row) * ROWB + (ks + a_k) * 2;
                ldm_x4(aH[i], sb + SM_A_HI + ra);
                ldm_x4(aL[i], sb + SM_A_LO + ra);
            }
#pragma unroll
            for (int p = 0; p < 4; p++) {
                uint32_t bh[4], bl[4];
                uint32_t rb = (64 * wn + 16 * p + b_row) * ROWB + (ks + b_k) * 2;
                ldm_x4(bh, sb + SM_B_HI + rb);
                ldm_x4(bl, sb + SM_B_LO + rb);
#pragma unroll
                for (int i = 0; i < 2; i++) {
#pragma unroll
                    for (int q = 0; q < 2; q++) {
                        float* c = acc[i][2 * p + q];
                        mma_bf16(c, aH[i], bh + 2 * q);
                        mma_bf16(c, aH[i], bl + 2 * q);
                        mma_bf16(c, aL[i], bh + 2 * q);
                    }
                }
            }
        }
        __syncthreads();
    }

    // epilogue: lane holds rows {gid, gid+8} of each m16 tile, cols 2*tig,+1 of each n8
    int gid = lane >> 2, tig = lane & 3;
#pragma unroll
    for (int i = 0; i < 2; i++) {
#pragma unroll
        for (int half = 0; half < 2; half++) {
            int m = 32 * wm + 16 * i + gid + 8 * half;
            if (mode == 0) {
                int grow = mbase + m;
                if (grow < Nrows) {
                    float* op = out + (size_t)grow * HDIM + nbg + 64 * wn;
                    const float* bp = bias + nbg + 64 * wn;
#pragma unroll
                    for (int j = 0; j < 8; j++) {
                        int c0 = 8 * j + 2 * tig;
                        op[c0]     = bp[c0]     + acc[i][j][2 * half];
                        op[c0 + 1] = bp[c0 + 1] + acc[i][j][2 * half + 1];
                    }
                }
            } else {
                int dv = ((const int*)(smem + SM_DST))[m];
                float sc = ((const float*)(smem + SM_INV))[m];
                if (dv >= 0) {
                    float* op = out + (size_t)dv * HDIM + nbg + 64 * wn;
#pragma unroll
                    for (int j = 0; j < 8; j++) {
                        int c0 = 8 * j + 2 * tig;
                        atomicAdd(&op[c0],     sc * acc[i][j][2 * half]);
                        atomicAdd(&op[c0 + 1], sc * acc[i][j][2 * half + 1]);
                    }
                }
            }
        }
    }
}

// ---------------- pooling (fused ReLU on h2) ------------------------------------
__global__ void k_pool(const float* __restrict__ h, const float* __restrict__ wsw,
                       const float* __restrict__ wsb, int N)
{
    int gtid = blockIdx.x * blockDim.x + threadIdx.x;
    int node = gtid >> 5;
    int lane = gtid & 31;
    if (node >= N) return;
    const float* hr = h + (size_t)node * HDIM;
    float hv[8];
    float dot = 0.f;
#pragma unroll
    for (int q = 0; q < 8; q++) {
        hv[q] = fmaxf(hr[lane + 32 * q], 0.f);
        dot += hv[q] * wsw[lane + 32 * q];
    }
#pragma unroll
    for (int o = 16; o > 0; o >>= 1) dot += __shfl_xor_sync(0xFFFFFFFFu, dot, o);
    float w = 1.f / (1.f + expf(-(dot + wsb[0])));
    float* er = g_emb + (size_t)g_batch[node] * HDIM;
#pragma unroll
    for (int q = 0; q < 8; q++) atomicAdd(&er[lane + 32 * q], w * hv[q]);
}

// ---------------- fused MLP head ------------------------------------------------
__global__ void k_mlp(const float* __restrict__ m1w, const float* __restrict__ m1b,
                      const float* __restrict__ m2w, const float* __restrict__ m2b,
                      const float* __restrict__ m3w, const float* __restrict__ m3b,
                      const float* __restrict__ ow,  const float* __restrict__ ob,
                      float* __restrict__ out)
{
    __shared__ float se[HDIM];
    __shared__ float s1[MDIM];
    __shared__ float s2[MDIM];
    __shared__ float sr[MDIM];
    int g = blockIdx.x;
    int t = threadIdx.x;
    for (int k = t; k < HDIM; k += MDIM) se[k] = g_emb[(size_t)g * HDIM + k];
    __syncthreads();
    float a = m1b[t];
    for (int k = 0; k < HDIM; k++) a += se[k] * m1w[k * MDIM + t];
    s1[t] = fmaxf(a, 0.f);
    __syncthreads();
    float b = m2b[t];
    for (int k = 0; k < MDIM; k++) b += s1[k] * m2w[k * MDIM + t];
    s2[t] = fmaxf(b, 0.f);
    __syncthreads();
    float c = m3b[t];
    for (int k = 0; k < MDIM; k++) c += s2[k] * m3w[k * MDIM + t];
    sr[t] = c * ow[t];
    __syncthreads();
    for (int o = 32; o > 0; o >>= 1) {
        if (t < o) sr[t] += sr[t + o];
        __syncthreads();
    }
    if (t == 0) out[g] = sr[0] + ob[0];
}

// ---------------- host side ------------------------------------------------------
extern "C" void kernel_launch(void* const* d_in, const int* in_sizes, int n_in,
                              void* d_out, int out_size)
{
    const float* x     = (const float*)d_in[0];
    const void*  eidx  = d_in[1];
    const void*  ety   = d_in[2];
    const void*  batch = d_in[3];
    const float* W1    = (const float*)d_in[4];
    const float* root1 = (const float*)d_in[5];
    const float* b1    = (const float*)d_in[6];
    const float* W2    = (const float*)d_in[7];
    const float* root2 = (const float*)d_in[8];
    const float* b2    = (const float*)d_in[9];
    const float* wsw   = (const float*)d_in[10];
    const float* wsb   = (const float*)d_in[11];
    const float* m1w   = (const float*)d_in[12];
    const float* m1b   = (const float*)d_in[13];
    const float* m2w   = (const float*)d_in[14];
    const float* m2b   = (const float*)d_in[15];
    const float* m3w   = (const float*)d_in[16];
    const float* m3b   = (const float*)d_in[17];
    const float* ow    = (const float*)d_in[18];
    const float* ob    = (const float*)d_in[19];
    float* out = (float*)d_out;

    int H = in_sizes[6];            // 256
    int F = in_sizes[5] / H;        // 128
    int N = in_sizes[0] / F;        // 50000
    int E = in_sizes[2];            // 200000
    int G = out_size;               // 1600

    float *p_h1, *p_h2;
    unsigned short *p_xhi, *p_xlo, *p_h1hi, *p_h1lo;
    unsigned short *p_w1thi, *p_w1tlo, *p_w2thi, *p_w2tlo;
    unsigned short *p_rt1hi, *p_rt1lo, *p_rt2hi, *p_rt2lo;
    cudaGetSymbolAddress((void**)&p_h1, g_h1);
    cudaGetSymbolAddress((void**)&p_h2, g_h2);
    cudaGetSymbolAddress((void**)&p_xhi, g_xhi);
    cudaGetSymbolAddress((void**)&p_xlo, g_xlo);
    cudaGetSymbolAddress((void**)&p_h1hi, g_h1hi);
    cudaGetSymbolAddress((void**)&p_h1lo, g_h1lo);
    cudaGetSymbolAddress((void**)&p_w1thi, g_w1thi);
    cudaGetSymbolAddress((void**)&p_w1tlo, g_w1tlo);
    cudaGetSymbolAddress((void**)&p_w2thi, g_w2thi);
    cudaGetSymbolAddress((void**)&p_w2tlo, g_w2tlo);
    cudaGetSymbolAddress((void**)&p_rt1hi, g_rt1hi);
    cudaGetSymbolAddress((void**)&p_rt1lo, g_rt1lo);
    cudaGetSymbolAddress((void**)&p_rt2hi, g_rt2hi);
    cudaGetSymbolAddress((void**)&p_rt2lo, g_rt2lo);

    cudaFuncSetAttribute(k_mma, cudaFuncAttributeMaxDynamicSharedMemorySize, SMEM_BYTES);

    // --- index normalization + counts + counting sort by relation ---
    k_detect<<<3, 256>>>(eidx, 2 * E, ety, E, batch, N);
    k_convert_edges<<<(E + 255) / 256, 256>>>(eidx, ety, E);
    k_convert_batch<<<(N + 255) / 256, 256>>>(batch, N);

    int ncnt = N * RNUM;
    k_zero_all<<<(ncnt + 255) / 256, 256>>>(ncnt, G * H);
    k_count<<<(E + N + 255) / 256, 256>>>(E, N);
    k_invert<<<(ncnt + 255) / 256, 256>>>(ncnt);
    k_scan_tiles<<<1, 1>>>(N);
    k_scatter<<<(E + N + 255) / 256, 256>>>(E, N);

    // --- bf16 splits: inputs + transposed weights ---
    k_split<<<(N * F + 255) / 256, 256>>>(x, p_xhi, p_xlo, N * F, 0);
    k_split_t<<<(RNUM * F * H + 255) / 256, 256>>>(W1, p_w1thi, p_w1tlo, RNUM, F);
    k_split_t<<<(RNUM * H * H + 255) / 256, 256>>>(W2, p_w2thi, p_w2tlo, RNUM, H);
    k_split_t<<<(F * H + 255) / 256, 256>>>(root1, p_rt1hi, p_rt1lo, 1, F);
    k_split_t<<<(H * H + 255) / 256, 256>>>(root2, p_rt2hi, p_rt2lo, 1, H);

    int ubTiles = (E + N + 127) / 128 + RNUM + 1;
    int ntilesN = (N + 127) / 128;

    // --- layer 1: h1 = b1 + X@root1 + edge(W1) ---
    k_mma<<<dim3(ntilesN, 2), 256, SMEM_BYTES>>>(p_xhi, p_xlo, p_rt1hi, p_rt1lo, b1, p_h1, F, 0, N);
    k_mma<<<dim3(ubTiles, 2), 256, SMEM_BYTES>>>(p_xhi, p_xlo, p_w1thi, p_w1tlo, nullptr, p_h1, F, 1, N);

    // --- relu(h1) -> bf16 split ---
    k_split<<<(N * H + 255) / 256, 256>>>(p_h1, p_h1hi, p_h1lo, N * H, 1);

    // --- layer 2: h2 = b2 + relu(h1)@root2 + edge(W2) ---
    k_mma<<<dim3(ntilesN, 2), 256, SMEM_BYTES>>>(p_h1hi, p_h1lo, p_rt2hi, p_rt2lo, b2, p_h2, H, 0, N);
    k_mma<<<dim3(ubTiles, 2), 256, SMEM_BYTES>>>(p_h1hi, p_h1lo, p_w2thi, p_w2tlo, nullptr, p_h2, H, 1, N);

    // --- weighted-sum pooling (ReLU fused) + MLP head ---
    k_pool<<<(N + 7) / 8, 256>>>(p_h2, wsw, wsb, N);
    k_mlp<<<G, MDIM>>>(m1w, m1b, m2w, m2b, m3w, m3b, ow, ob, out);
}

// round 11
// speedup vs baseline: 1.7880x; 1.6717x over previous
#include <cuda_runtime.h>
#include <cuda_bf16.h>
#include <math.h>
#include <stdint.h>

// Problem-fixed sizes.
#define NNODE 50000
#define EEDGE 200000
#define ESMAX (EEDGE + NNODE)
#define RNUM 65
#define FDIM 128
#define HDIM 256
#define GNUM 1600
#define MDIM 64
#define MAXTILES 4096

// ---------------- device scratch (allocation-free rule: __device__ globals) ----
__device__ int   g_flag64[3];
__device__ int   g_esrc[EEDGE];
__device__ int   g_edst[EEDGE];
__device__ int   g_etype[EEDGE];
__device__ int   g_batch[NNODE];
__device__ float g_cnt[NNODE * RNUM];
__device__ int   g_hist[RNUM];
__device__ int   g_cursor[RNUM];
__device__ int   g_ts[MAXTILES];
__device__ int   g_tc[MAXTILES];
__device__ int   g_tr[MAXTILES];
__device__ int   g_ntiles;
__device__ int   g_src[ESMAX];
__device__ int   g_dst[ESMAX];
__device__ float g_h1[(size_t)NNODE * HDIM];
__device__ float g_h2[(size_t)NNODE * HDIM];
__device__ float g_emb[GNUM * HDIM];

// bf16 hi/lo split buffers (Dekker split: x = hi + lo)
__device__ __align__(16) unsigned short g_xhi[(size_t)NNODE * FDIM];
__device__ __align__(16) unsigned short g_xlo[(size_t)NNODE * FDIM];
__device__ __align__(16) unsigned short g_h1hi[(size_t)NNODE * HDIM];
__device__ __align__(16) unsigned short g_h1lo[(size_t)NNODE * HDIM];
// transposed weights: [r][n(256)][k]  (K-major rows = "col" operand for mma)
__device__ __align__(16) unsigned short g_w1thi[(size_t)RNUM * HDIM * FDIM];
__device__ __align__(16) unsigned short g_w1tlo[(size_t)RNUM * HDIM * FDIM];
__device__ __align__(16) unsigned short g_w2thi[(size_t)RNUM * HDIM * HDIM];
__device__ __align__(16) unsigned short g_w2tlo[(size_t)RNUM * HDIM * HDIM];
__device__ __align__(16) unsigned short g_rt1hi[HDIM * FDIM];
__device__ __align__(16) unsigned short g_rt1lo[HDIM * FDIM];
__device__ __align__(16) unsigned short g_rt2hi[HDIM * HDIM];
__device__ __align__(16) unsigned short g_rt2lo[HDIM * HDIM];

// ---------------- PTX helpers (sm_80-era features only: compile for compute_103)
__device__ __forceinline__ uint32_t smem_u32(const void* p)
{
    uint32_t a;
    asm("{ .reg .u64 t; cvta.to.shared.u64 t, %1; cvt.u32.u64 %0, t; }"
        : "=r"(a) : "l"(p));
    return a;
}

__device__ __forceinline__ void ldm_x4(uint32_t* r, uint32_t addr)
{
    asm volatile("ldmatrix.sync.aligned.m8n8.x4.shared.b16 {%0,%1,%2,%3}, [%4];"
                 : "=r"(r[0]), "=r"(r[1]), "=r"(r[2]), "=r"(r[3]) : "r"(addr));
}

__device__ __forceinline__ void mma_bf16(float* c, const uint32_t* a, const uint32_t* b)
{
    asm volatile(
        "mma.sync.aligned.m16n8k16.row.col.f32.bf16.bf16.f32 "
        "{%0,%1,%2,%3}, {%4,%5,%6,%7}, {%8,%9}, {%0,%1,%2,%3};"
        : "+f"(c[0]), "+f"(c[1]), "+f"(c[2]), "+f"(c[3])
        : "r"(a[0]), "r"(a[1]), "r"(a[2]), "r"(a[3]), "r"(b[0]), "r"(b[1]));
}

__device__ __forceinline__ void cp16(uint32_t saddr, const void* gaddr)
{
    asm volatile("cp.async.cg.shared.global [%0], [%1], 16;"
                 :: "r"(saddr), "l"(gaddr));
}

// ---------------- setup kernels -------------------------------------------------
__global__ void k_detect(const void* p0, int n0, const void* p1, int n1,
                         const void* p2, int n2)
{
    const unsigned int* p;
    int n;
    int b = blockIdx.x;
    if (b == 0)      { p = (const unsigned int*)p0; n = n0; }
    else if (b == 1) { p = (const unsigned int*)p1; n = n1; }
    else             { p = (const unsigned int*)p2; n = n2; }
    __shared__ int s_nz;
    if (threadIdx.x == 0) s_nz = 0;
    __syncthreads();
    int kmax = (n - 1) >> 1;
    if (kmax > 0) {
        int k = (int)(((long long)threadIdx.x * kmax) >> 8);
        if (p[2 * k + 1] != 0u) s_nz = 1;
    }
    __syncthreads();
    if (threadIdx.x == 0) g_flag64[b] = s_nz ? 0 : 1;
}

__global__ void k_convert_edges(const void* eidx, const void* ety, int E)
{
    int i = blockIdx.x * blockDim.x + threadIdx.x;
    if (i >= E) return;
    if (g_flag64[0]) {
        const long long* p = (const long long*)eidx;
        g_esrc[i] = (int)p[i];
        g_edst[i] = (int)p[E + i];
    } else {
        const int* p = (const int*)eidx;
        g_esrc[i] = p[i];
        g_edst[i] = p[E + i];
    }
    g_etype[i] = g_flag64[1] ? (int)((const long long*)ety)[i]
                             : ((const int*)ety)[i];
}

__global__ void k_convert_batch(const void* batch, int N)
{
    int i = blockIdx.x * blockDim.x + threadIdx.x;
    if (i >= N) return;
    g_batch[i] = g_flag64[2] ? (int)((const long long*)batch)[i]
                             : ((const int*)batch)[i];
}

__global__ void k_zero_all(int ncnt, int nemb)
{
    int i = blockIdx.x * blockDim.x + threadIdx.x;
    if (i < ncnt) g_cnt[i] = 0.f;
    if (i < nemb) g_emb[i] = 0.f;
    if (i < RNUM) g_hist[i] = 0;
}

__global__ void k_count(int E, int N)
{
    int i = blockIdx.x * blockDim.x + threadIdx.x;
    if (i < E) {
        int r = g_etype[i];
        atomicAdd(&g_cnt[g_edst[i] * RNUM + r], 1.f);
        atomicAdd(&g_hist[r], 1);
    } else if (i < E + N) {
        atomicAdd(&g_cnt[(i - E) * RNUM], 1.f);  // self loop, relation 0
    }
}

__global__ void k_invert(int n)
{
    int i = blockIdx.x * blockDim.x + threadIdx.x;
    if (i < n) g_cnt[i] = 1.f / fmaxf(g_cnt[i], 1.f);
}

__global__ void k_scan_tiles(int N)
{
    if (blockIdx.x != 0 || threadIdx.x != 0) return;
    int off = 0, nt = 0;
    for (int r = 0; r < RNUM; r++) {
        int c = g_hist[r] + (r == 0 ? N : 0);
        g_cursor[r] = off;
        for (int s = 0; s < c; s += 128) {
            g_ts[nt] = off + s;
            g_tc[nt] = (c - s < 128) ? (c - s) : 128;
            g_tr[nt] = r;
            nt++;
        }
        off += c;
    }
    g_ntiles = nt;
}

__global__ void k_scatter(int E, int N)
{
    int i = blockIdx.x * blockDim.x + threadIdx.x;
    if (i < E) {
        int r = g_etype[i];
        int p = atomicAdd(&g_cursor[r], 1);
        g_src[p] = g_esrc[i];
        g_dst[p] = g_edst[i];
    } else if (i < E + N) {
        int v = i - E;
        int p = atomicAdd(&g_cursor[0], 1);
        g_src[p] = v;
        g_dst[p] = v;
    }
}

// ---------------- bf16 split conversions ---------------------------------------
__global__ void k_split(const float* __restrict__ src, unsigned short* __restrict__ hi,
                        unsigned short* __restrict__ lo, int n, int do_relu)
{
    int i = blockIdx.x * blockDim.x + threadIdx.x;
    if (i >= n) return;
    float v = src[i];
    if (do_relu) v = fmaxf(v, 0.f);
    __nv_bfloat16 h = __float2bfloat16(v);
    float r = v - __bfloat162float(h);
    __nv_bfloat16 l = __float2bfloat16(r);
    hi[i] = *(unsigned short*)&h;
    lo[i] = *(unsigned short*)&l;
}

// W: [R][K][256] -> out: [R][256][K], split
__global__ void k_split_t(const float* __restrict__ W, unsigned short* __restrict__ hi,
                          unsigned short* __restrict__ lo, int R, int K)
{
    int i = blockIdx.x * blockDim.x + threadIdx.x;
    int tot = R * K * 256;
    if (i >= tot) return;
    int n = i & 255;
    int k = (i >> 8) % K;
    int r = i / (K * 256);
    float v = W[i];
    __nv_bfloat16 h = __float2bfloat16(v);
    float rr = v - __bfloat162float(h);
    __nv_bfloat16 l = __float2bfloat16(rr);
    size_t o = ((size_t)r * 256 + n) * K + k;
    hi[o] = *(unsigned short*)&h;
    lo[o] = *(unsigned short*)&l;
}

// ---------------- HMMA GEMM: dense (mode 0) / edge gather-scatter (mode 1) -----
// Block tile: 128 rows x 128 cols (grid.y selects 128-col half of HDIM=256).
// 8 warps = 4 (m) x 2 (n); warp tile 32 x 64. K staged 32-wide in SMEM,
// cp.async double-buffered (issue s+1 while computing s).
// D = Ahi*Bhi + Ahi*Blo + Alo*Bhi via mma.sync m16n8k16 bf16 (Dekker split).
// SMEM row stride 80 B: 8 consecutive row addrs land on distinct 16B groups
// mod 128 -> ldmatrix conflict-free.
#define SM_SRC  0
#define SM_DST  512
#define SM_INV  1024
#define SM_TILE 2048
#define ARRB    10240               // one array: 128 rows x 80 B
#define BUFB    (4 * ARRB)          // Ahi,Alo,Bhi,Blo
#define SMEM_BYTES (SM_TILE + 2 * BUFB)   // 83968
#define ROWB 80

__global__ __launch_bounds__(256) void k_mma(
    const unsigned short* __restrict__ Ahi, const unsigned short* __restrict__ Alo,
    const unsigned short* __restrict__ Bhi_all, const unsigned short* __restrict__ Blo_all,
    const float* __restrict__ bias, float* __restrict__ out,
    int K, int mode, int Nrows)
{
    extern __shared__ char smem[];
    uint32_t sb = smem_u32(smem);
    int tid = threadIdx.x;
    int wid = tid >> 5;
    int lane = tid & 31;
    int nbg = blockIdx.y * 128;   // global col base of this block

    int mbase = 0;
    const unsigned short *Bhi, *Blo;
    if (mode == 0) {
        mbase = blockIdx.x * 128;
        Bhi = Bhi_all + (size_t)nbg * K;
        Blo = Blo_all + (size_t)nbg * K;
        if (tid < 128) {
            int grow = mbase + tid;
            if (grow >= Nrows) grow = Nrows - 1;
            ((int*)(smem + SM_SRC))[tid] = grow;
        }
    } else {
        int t = blockIdx.x;
        if (t >= g_ntiles) return;
        int start = g_ts[t], cnt = g_tc[t], rel = g_tr[t];
        Bhi = Bhi_all + ((size_t)rel * 256 + nbg) * K;
        Blo = Blo_all + ((size_t)rel * 256 + nbg) * K;
        if (tid < 128) {
            if (tid < cnt) {
                int e = start + tid;
                int dv = g_dst[e];
                ((int*)(smem + SM_SRC))[tid] = g_src[e];
                ((int*)(smem + SM_DST))[tid] = dv;
                ((float*)(smem + SM_INV))[tid] = g_cnt[dv * RNUM + rel];
            } else {
                ((int*)(smem + SM_SRC))[tid] = g_src[start];
                ((int*)(smem + SM_DST))[tid] = -1;
                ((float*)(smem + SM_INV))[tid] = 0.f;
            }
        }
    }
    __syncthreads();
    const int* s_src = (const int*)(smem + SM_SRC);

    int wm = wid & 3, wn = wid >> 2;
    int a_row = lane & 15;
    int a_k   = (lane >> 4) * 8;
    int b_row = ((lane >> 4) * 8) + (lane & 7);
    int b_k   = ((lane >> 3) & 1) * 8;

    float acc[2][8][4];
#pragma unroll
    for (int i = 0; i < 2; i++)
#pragma unroll
        for (int j = 0; j < 8; j++)
#pragma unroll
            for (int q = 0; q < 4; q++) acc[i][j][q] = 0.f;

    int nst = K >> 5;   // K32 chunks

    // stage issue: 2048 16B segments (4 arrays x 128 rows x 4 segs), 8/thread
    auto issue = [&](int s, int pb) {
        int kb = s << 5;
        uint32_t tb = sb + SM_TILE + pb * BUFB;
#pragma unroll
        for (int u = tid; u < 2048; u += 256) {
            int arr = u >> 9;           // 0 Ahi, 1 Alo, 2 Bhi, 3 Blo
            int v = u & 511;
            int row = v >> 2, seg = v & 3;
            const unsigned short* gp;
            if (arr == 0)      gp = Ahi + (size_t)s_src[row] * K;
            else if (arr == 1) gp = Alo + (size_t)s_src[row] * K;
            else if (arr == 2) gp = Bhi + (size_t)row * K;
            else               gp = Blo + (size_t)row * K;
            cp16(tb + arr * ARRB + row * ROWB + seg * 16, gp + kb + seg * 8);
        }
        asm volatile("cp.async.commit_group;" ::: "memory");
    };

    issue(0, 0);
    for (int s = 0; s < nst; s++) {
        int pb = s & 1;
        if (s + 1 < nst) {
            issue(s + 1, pb ^ 1);
            asm volatile("cp.async.wait_group 1;" ::: "memory");
        } else {
            asm volatile("cp.async.wait_group 0;" ::: "memory");
        }
        __syncthreads();

        uint32_t tb = sb + SM_TILE + pb * BUFB;
#pragma unroll
        for (int ks = 0; ks < 32; ks += 16) {
            uint32_t aH[2][4], aL[2][4];
#pragma unroll
            for (int i = 0; i < 2; i++) {
                uint32_t ra = (32 * wm + 16 * i + a_row) * ROWB + (ks + a_k) * 2;
                ldm_x4(aH[i], tb + 0 * ARRB + ra);
                ldm_x4(aL[i], tb + 1 * ARRB + ra);
            }
#pragma unroll
            for (int p4 = 0; p4 < 4; p4++) {
                uint32_t bh[4], bl[4];
                uint32_t rb = (64 * wn + 16 * p4 + b_row) * ROWB + (ks + b_k) * 2;
                ldm_x4(bh, tb + 2 * ARRB + rb);
                ldm_x4(bl, tb + 3 * ARRB + rb);
#pragma unroll
                for (int i = 0; i < 2; i++) {
#pragma unroll
                    for (int q = 0; q < 2; q++) {
                        float* c = acc[i][2 * p4 + q];
                        mma_bf16(c, aH[i], bh + 2 * q);
                        mma_bf16(c, aH[i], bl + 2 * q);
                        mma_bf16(c, aL[i], bh + 2 * q);
                    }
                }
            }
        }
        __syncthreads();
    }

    // epilogue: lane holds rows {gid, gid+8} of each m16 tile, cols 2*tig,+1 of each n8
    int gid = lane >> 2, tig = lane & 3;
#pragma unroll
    for (int i = 0; i < 2; i++) {
#pragma unroll
        for (int half = 0; half < 2; half++) {
            int m = 32 * wm + 16 * i + gid + 8 * half;
            if (mode == 0) {
                int grow = mbase + m;
                if (grow < Nrows) {
                    float* op = out + (size_t)grow * HDIM + nbg + 64 * wn;
                    const float* bp = bias + nbg + 64 * wn;
#pragma unroll
                    for (int j = 0; j < 8; j++) {
                        int c0 = 8 * j + 2 * tig;
                        op[c0]     = bp[c0]     + acc[i][j][2 * half];
                        op[c0 + 1] = bp[c0 + 1] + acc[i][j][2 * half + 1];
                    }
                }
            } else {
                int dv = ((const int*)(smem + SM_DST))[m];
                float sc = ((const float*)(smem + SM_INV))[m];
                if (dv >= 0) {
                    float* op = out + (size_t)dv * HDIM + nbg + 64 * wn;
#pragma unroll
                    for (int j = 0; j < 8; j++) {
                        int c0 = 8 * j + 2 * tig;
                        atomicAdd(&op[c0],     sc * acc[i][j][2 * half]);
                        atomicAdd(&op[c0 + 1], sc * acc[i][j][2 * half + 1]);
                    }
                }
            }
        }
    }
}

// ---------------- pooling (fused ReLU on h2) ------------------------------------
__global__ void k_pool(const float* __restrict__ h, const float* __restrict__ wsw,
                       const float* __restrict__ wsb, int N)
{
    int gtid = blockIdx.x * blockDim.x + threadIdx.x;
    int node = gtid >> 5;
    int lane = gtid & 31;
    if (node >= N) return;
    const float* hr = h + (size_t)node * HDIM;
    float hv[8];
    float dot = 0.f;
#pragma unroll
    for (int q = 0; q < 8; q++) {
        hv[q] = fmaxf(hr[lane + 32 * q], 0.f);
        dot += hv[q] * wsw[lane + 32 * q];
    }
#pragma unroll
    for (int o = 16; o > 0; o >>= 1) dot += __shfl_xor_sync(0xFFFFFFFFu, dot, o);
    float w = 1.f / (1.f + expf(-(dot + wsb[0])));
    float* er = g_emb + (size_t)g_batch[node] * HDIM;
#pragma unroll
    for (int q = 0; q < 8; q++) atomicAdd(&er[lane + 32 * q], w * hv[q]);
}

// ---------------- fused MLP head ------------------------------------------------
__global__ void k_mlp(const float* __restrict__ m1w, const float* __restrict__ m1b,
                      const float* __restrict__ m2w, const float* __restrict__ m2b,
                      const float* __restrict__ m3w, const float* __restrict__ m3b,
                      const float* __restrict__ ow,  const float* __restrict__ ob,
                      float* __restrict__ out)
{
    __shared__ float se[HDIM];
    __shared__ float s1[MDIM];
    __shared__ float s2[MDIM];
    __shared__ float sr[MDIM];
    int g = blockIdx.x;
    int t = threadIdx.x;
    for (int k = t; k < HDIM; k += MDIM) se[k] = g_emb[(size_t)g * HDIM + k];
    __syncthreads();
    float a = m1b[t];
    for (int k = 0; k < HDIM; k++) a += se[k] * m1w[k * MDIM + t];
    s1[t] = fmaxf(a, 0.f);
    __syncthreads();
    float b = m2b[t];
    for (int k = 0; k < MDIM; k++) b += s1[k] * m2w[k * MDIM + t];
    s2[t] = fmaxf(b, 0.f);
    __syncthreads();
    float c = m3b[t];
    for (int k = 0; k < MDIM; k++) c += s2[k] * m3w[k * MDIM + t];
    sr[t] = c * ow[t];
    __syncthreads();
    for (int o = 32; o > 0; o >>= 1) {
        if (t < o) sr[t] += sr[t + o];
        __syncthreads();
    }
    if (t == 0) out[g] = sr[0] + ob[0];
}

// ---------------- host side ------------------------------------------------------
extern "C" void kernel_launch(void* const* d_in, const int* in_sizes, int n_in,
                              void* d_out, int out_size)
{
    const float* x     = (const float*)d_in[0];
    const void*  eidx  = d_in[1];
    const void*  ety   = d_in[2];
    const void*  batch = d_in[3];
    const float* W1    = (const float*)d_in[4];
    const float* root1 = (const float*)d_in[5];
    const float* b1    = (const float*)d_in[6];
    const float* W2    = (const float*)d_in[7];
    const float* root2 = (const float*)d_in[8];
    const float* b2    = (const float*)d_in[9];
    const float* wsw   = (const float*)d_in[10];
    const float* wsb   = (const float*)d_in[11];
    const float* m1w   = (const float*)d_in[12];
    const float* m1b   = (const float*)d_in[13];
    const float* m2w   = (const float*)d_in[14];
    const float* m2b   = (const float*)d_in[15];
    const float* m3w   = (const float*)d_in[16];
    const float* m3b   = (const float*)d_in[17];
    const float* ow    = (const float*)d_in[18];
    const float* ob    = (const float*)d_in[19];
    float* out = (float*)d_out;

    int H = in_sizes[6];            // 256
    int F = in_sizes[5] / H;        // 128
    int N = in_sizes[0] / F;        // 50000
    int E = in_sizes[2];            // 200000
    int G = out_size;               // 1600

    float *p_h1, *p_h2;
    unsigned short *p_xhi, *p_xlo, *p_h1hi, *p_h1lo;
    unsigned short *p_w1thi, *p_w1tlo, *p_w2thi, *p_w2tlo;
    unsigned short *p_rt1hi, *p_rt1lo, *p_rt2hi, *p_rt2lo;
    cudaGetSymbolAddress((void**)&p_h1, g_h1);
    cudaGetSymbolAddress((void**)&p_h2, g_h2);
    cudaGetSymbolAddress((void**)&p_xhi, g_xhi);
    cudaGetSymbolAddress((void**)&p_xlo, g_xlo);
    cudaGetSymbolAddress((void**)&p_h1hi, g_h1hi);
    cudaGetSymbolAddress((void**)&p_h1lo, g_h1lo);
    cudaGetSymbolAddress((void**)&p_w1thi, g_w1thi);
    cudaGetSymbolAddress((void**)&p_w1tlo, g_w1tlo);
    cudaGetSymbolAddress((void**)&p_w2thi, g_w2thi);
    cudaGetSymbolAddress((void**)&p_w2tlo, g_w2tlo);
    cudaGetSymbolAddress((void**)&p_rt1hi, g_rt1hi);
    cudaGetSymbolAddress((void**)&p_rt1lo, g_rt1lo);
    cudaGetSymbolAddress((void**)&p_rt2hi, g_rt2hi);
    cudaGetSymbolAddress((void**)&p_rt2lo, g_rt2lo);

    cudaFuncSetAttribute(k_mma, cudaFuncAttributeMaxDynamicSharedMemorySize, SMEM_BYTES);

    // --- index normalization + counts + counting sort by relation ---
    k_detect<<<3, 256>>>(eidx, 2 * E, ety, E, batch, N);
    k_convert_edges<<<(E + 255) / 256, 256>>>(eidx, ety, E);
    k_convert_batch<<<(N + 255) / 256, 256>>>(batch, N);

    int ncnt = N * RNUM;
    k_zero_all<<<(ncnt + 255) / 256, 256>>>(ncnt, G * H);
    k_count<<<(E + N + 255) / 256, 256>>>(E, N);
    k_invert<<<(ncnt + 255) / 256, 256>>>(ncnt);
    k_scan_tiles<<<1, 1>>>(N);
    k_scatter<<<(E + N + 255) / 256, 256>>>(E, N);

    // --- bf16 splits: inputs + transposed weights ---
    k_split<<<(N * F + 255) / 256, 256>>>(x, p_xhi, p_xlo, N * F, 0);
    k_split_t<<<(RNUM * F * H + 255) / 256, 256>>>(W1, p_w1thi, p_w1tlo, RNUM, F);
    k_split_t<<<(RNUM * H * H + 255) / 256, 256>>>(W2, p_w2thi, p_w2tlo, RNUM, H);
    k_split_t<<<(F * H + 255) / 256, 256>>>(root1, p_rt1hi, p_rt1lo, 1, F);
    k_split_t<<<(H * H + 255) / 256, 256>>>(root2, p_rt2hi, p_rt2lo, 1, H);

    int ubTiles = (E + N + 127) / 128 + RNUM + 1;
    int ntilesN = (N + 127) / 128;

    // --- layer 1: h1 = b1 + X@root1 + edge(W1) ---
    k_mma<<<dim3(ntilesN, 2), 256, SMEM_BYTES>>>(p_xhi, p_xlo, p_rt1hi, p_rt1lo, b1, p_h1, F, 0, N);
    k_mma<<<dim3(ubTiles, 2), 256, SMEM_BYTES>>>(p_xhi, p_xlo, p_w1thi, p_w1tlo, nullptr, p_h1, F, 1, N);

    // --- relu(h1) -> bf16 split ---
    k_split<<<(N * H + 255) / 256, 256>>>(p_h1, p_h1hi, p_h1lo, N * H, 1);

    // --- layer 2: h2 = b2 + relu(h1)@root2 + edge(W2) ---
    k_mma<<<dim3(ntilesN, 2), 256, SMEM_BYTES>>>(p_h1hi, p_h1lo, p_rt2hi, p_rt2lo, b2, p_h2, H, 0, N);
    k_mma<<<dim3(ubTiles, 2), 256, SMEM_BYTES>>>(p_h1hi, p_h1lo, p_w2thi, p_w2tlo, nullptr, p_h2, H, 1, N);

    // --- weighted-sum pooling (ReLU fused) + MLP head ---
    k_pool<<<(N + 7) / 8, 256>>>(p_h2, wsw, wsb, N);
    k_mlp<<<G, MDIM>>>(m1w, m1b, m2w, m2b, m3w, m3b, ow, ob, out);
}

// round 14
// speedup vs baseline: 1.8337x; 1.0255x over previous
#include <cuda_runtime.h>
#include <cuda_bf16.h>
#include <math.h>
#include <stdint.h>

// Problem-fixed sizes.
#define NNODE 50000
#define EEDGE 200000
#define ESMAX (EEDGE + NNODE)
#define RNUM 65
#define FDIM 128
#define HDIM 256
#define GNUM 1600
#define MDIM 64
#define MAXTILES 4096

// ---------------- device scratch (allocation-free rule: __device__ globals) ----
__device__ int   g_flag64[3];
__device__ int   g_esrc[EEDGE];
__device__ int   g_edst[EEDGE];
__device__ int   g_etype[EEDGE];
__device__ int   g_batch[NNODE];
__device__ float g_cnt[NNODE * RNUM];
__device__ int   g_hist[RNUM];
__device__ int   g_cursor[RNUM];
__device__ int   g_ts[MAXTILES];
__device__ int   g_tc[MAXTILES];
__device__ int   g_tr[MAXTILES];
__device__ int   g_ntiles;
__device__ int   g_src[ESMAX];
__device__ int   g_dst[ESMAX];
__device__ float g_h1[(size_t)NNODE * HDIM];
__device__ float g_h2[(size_t)NNODE * HDIM];
__device__ float g_emb[GNUM * HDIM];

// bf16 hi/lo split buffers (Dekker split: x = hi + lo)
__device__ __align__(16) unsigned short g_xhi[(size_t)NNODE * FDIM];
__device__ __align__(16) unsigned short g_xlo[(size_t)NNODE * FDIM];
__device__ __align__(16) unsigned short g_h1hi[(size_t)NNODE * HDIM];
__device__ __align__(16) unsigned short g_h1lo[(size_t)NNODE * HDIM];
// transposed weights: [r][n(256)][k]  (K-major rows = "col" operand for mma)
__device__ __align__(16) unsigned short g_w1thi[(size_t)RNUM * HDIM * FDIM];
__device__ __align__(16) unsigned short g_w1tlo[(size_t)RNUM * HDIM * FDIM];
__device__ __align__(16) unsigned short g_w2thi[(size_t)RNUM * HDIM * HDIM];
__device__ __align__(16) unsigned short g_w2tlo[(size_t)RNUM * HDIM * HDIM];
__device__ __align__(16) unsigned short g_rt1hi[HDIM * FDIM];
__device__ __align__(16) unsigned short g_rt1lo[HDIM * FDIM];
__device__ __align__(16) unsigned short g_rt2hi[HDIM * HDIM];
__device__ __align__(16) unsigned short g_rt2lo[HDIM * HDIM];

// ---------------- PTX helpers (sm_80/sm_90 plain features: compile for compute_103)
__device__ __forceinline__ uint32_t smem_u32(const void* p)
{
    uint32_t a;
    asm("{ .reg .u64 t; cvta.to.shared.u64 t, %1; cvt.u32.u64 %0, t; }"
        : "=r"(a) : "l"(p));
    return a;
}

__device__ __forceinline__ void ldm_x4(uint32_t* r, uint32_t addr)
{
    asm volatile("ldmatrix.sync.aligned.m8n8.x4.shared.b16 {%0,%1,%2,%3}, [%4];"
                 : "=r"(r[0]), "=r"(r[1]), "=r"(r[2]), "=r"(r[3]) : "r"(addr));
}

__device__ __forceinline__ void mma_bf16(float* c, const uint32_t* a, const uint32_t* b)
{
    asm volatile(
        "mma.sync.aligned.m16n8k16.row.col.f32.bf16.bf16.f32 "
        "{%0,%1,%2,%3}, {%4,%5,%6,%7}, {%8,%9}, {%0,%1,%2,%3};"
        : "+f"(c[0]), "+f"(c[1]), "+f"(c[2]), "+f"(c[3])
        : "r"(a[0]), "r"(a[1]), "r"(a[2]), "r"(a[3]), "r"(b[0]), "r"(b[1]));
}

__device__ __forceinline__ void cp16(uint32_t saddr, const void* gaddr)
{
    asm volatile("cp.async.cg.shared.global [%0], [%1], 16;"
                 :: "r"(saddr), "l"(gaddr));
}

// vectorized fp32 pair reduction (PTX ISA 8.1+, sm_90+ plain)
__device__ __forceinline__ void red2(float* addr, float v0, float v1)
{
    asm volatile("red.global.add.v2.f32 [%0], {%1, %2};"
                 :: "l"(addr), "f"(v0), "f"(v1) : "memory");
}

// ---------------- setup kernels -------------------------------------------------
__global__ void k_detect(const void* p0, int n0, const void* p1, int n1,
                         const void* p2, int n2)
{
    const unsigned int* p;
    int n;
    int b = blockIdx.x;
    if (b == 0)      { p = (const unsigned int*)p0; n = n0; }
    else if (b == 1) { p = (const unsigned int*)p1; n = n1; }
    else             { p = (const unsigned int*)p2; n = n2; }
    __shared__ int s_nz;
    if (threadIdx.x == 0) s_nz = 0;
    __syncthreads();
    int kmax = (n - 1) >> 1;
    if (kmax > 0) {
        int k = (int)(((long long)threadIdx.x * kmax) >> 8);
        if (p[2 * k + 1] != 0u) s_nz = 1;
    }
    __syncthreads();
    if (threadIdx.x == 0) g_flag64[b] = s_nz ? 0 : 1;
}

__global__ void k_convert_edges(const void* eidx, const void* ety, int E)
{
    int i = blockIdx.x * blockDim.x + threadIdx.x;
    if (i >= E) return;
    if (g_flag64[0]) {
        const long long* p = (const long long*)eidx;
        g_esrc[i] = (int)p[i];
        g_edst[i] = (int)p[E + i];
    } else {
        const int* p = (const int*)eidx;
        g_esrc[i] = p[i];
        g_edst[i] = p[E + i];
    }
    g_etype[i] = g_flag64[1] ? (int)((const long long*)ety)[i]
                             : ((const int*)ety)[i];
}

__global__ void k_convert_batch(const void* batch, int N)
{
    int i = blockIdx.x * blockDim.x + threadIdx.x;
    if (i >= N) return;
    g_batch[i] = g_flag64[2] ? (int)((const long long*)batch)[i]
                             : ((const int*)batch)[i];
}

__global__ void k_zero_all(int ncnt, int nemb)
{
    int i = blockIdx.x * blockDim.x + threadIdx.x;
    if (i < ncnt) g_cnt[i] = 0.f;
    if (i < nemb) g_emb[i] = 0.f;
    if (i < RNUM) g_hist[i] = 0;
}

__global__ void k_count(int E, int N)
{
    int i = blockIdx.x * blockDim.x + threadIdx.x;
    if (i < E) {
        int r = g_etype[i];
        atomicAdd(&g_cnt[g_edst[i] * RNUM + r], 1.f);
        atomicAdd(&g_hist[r], 1);
    } else if (i < E + N) {
        atomicAdd(&g_cnt[(i - E) * RNUM], 1.f);  // self loop, relation 0
    }
}

__global__ void k_invert(int n)
{
    int i = blockIdx.x * blockDim.x + threadIdx.x;
    if (i < n) g_cnt[i] = 1.f / fmaxf(g_cnt[i], 1.f);
}

// parallel tile build: thread r owns relation r
__global__ void k_scan_tiles(int N)
{
    __shared__ int sc[RNUM], st[RNUM], so[RNUM], sto[RNUM];
    int t = threadIdx.x;
    if (t < RNUM) {
        int c = g_hist[t] + (t == 0 ? N : 0);
        sc[t] = c;
        st[t] = (c + 127) >> 7;
    }
    __syncthreads();
    if (t == 0) {
        int eo = 0, to = 0;
        for (int r = 0; r < RNUM; r++) {
            so[r] = eo; sto[r] = to;
            eo += sc[r]; to += st[r];
        }
        g_ntiles = to;
    }
    __syncthreads();
    if (t < RNUM) {
        g_cursor[t] = so[t];
        int base = so[t], nt = st[t], tb = sto[t], c = sc[t];
        for (int i = 0; i < nt; i++) {
            g_ts[tb + i] = base + i * 128;
            int rem = c - i * 128;
            g_tc[tb + i] = rem < 128 ? rem : 128;
            g_tr[tb + i] = t;
        }
    }
}

__global__ void k_scatter(int E, int N)
{
    int i = blockIdx.x * blockDim.x + threadIdx.x;
    if (i < E) {
        int r = g_etype[i];
        int p = atomicAdd(&g_cursor[r], 1);
        g_src[p] = g_esrc[i];
        g_dst[p] = g_edst[i];
    } else if (i < E + N) {
        int v = i - E;
        int p = atomicAdd(&g_cursor[0], 1);
        g_src[p] = v;
        g_dst[p] = v;
    }
}

// ---------------- bf16 split conversions ---------------------------------------
__global__ void k_split(const float* __restrict__ src, unsigned short* __restrict__ hi,
                        unsigned short* __restrict__ lo, int n, int do_relu)
{
    int i = blockIdx.x * blockDim.x + threadIdx.x;
    if (i >= n) return;
    float v = src[i];
    if (do_relu) v = fmaxf(v, 0.f);
    __nv_bfloat16 h = __float2bfloat16(v);
    float r = v - __bfloat162float(h);
    __nv_bfloat16 l = __float2bfloat16(r);
    hi[i] = *(unsigned short*)&h;
    lo[i] = *(unsigned short*)&l;
}

// W: [R][K][256] -> out: [R][256][K], split
__global__ void k_split_t(const float* __restrict__ W, unsigned short* __restrict__ hi,
                          unsigned short* __restrict__ lo, int R, int K)
{
    int i = blockIdx.x * blockDim.x + threadIdx.x;
    int tot = R * K * 256;
    if (i >= tot) return;
    int n = i & 255;
    int k = (i >> 8) % K;
    int r = i / (K * 256);
    float v = W[i];
    __nv_bfloat16 h = __float2bfloat16(v);
    float rr = v - __bfloat162float(h);
    __nv_bfloat16 l = __float2bfloat16(rr);
    size_t o = ((size_t)r * 256 + n) * K + k;
    hi[o] = *(unsigned short*)&h;
    lo[o] = *(unsigned short*)&l;
}

// ---------------- HMMA GEMM: dense (mode 0) / edge gather-scatter (mode 1) -----
// Block tile: 128 rows x 128 cols (grid.y selects 128-col half of HDIM=256).
// 8 warps = 4 (m) x 2 (n); warp tile 32 x 64. K staged 32-wide in SMEM,
// cp.async double-buffered (issue s+1 while computing s).
// D = Ahi*Bhi + Ahi*Blo + Alo*Bhi via mma.sync m16n8k16 bf16 (Dekker split).
// SMEM row stride 80 B: 8 consecutive row addrs land on distinct 16B groups
// mod 128 -> ldmatrix conflict-free. Edge epilogue: red.global.add.v2.f32.
#define SM_SRC  0
#define SM_DST  512
#define SM_INV  1024
#define SM_TILE 2048
#define ARRB    10240               // one array: 128 rows x 80 B
#define BUFB    (4 * ARRB)          // Ahi,Alo,Bhi,Blo
#define SMEM_BYTES (SM_TILE + 2 * BUFB)   // 83968
#define ROWB 80

__global__ __launch_bounds__(256) void k_mma(
    const unsigned short* __restrict__ Ahi, const unsigned short* __restrict__ Alo,
    const unsigned short* __restrict__ Bhi_all, const unsigned short* __restrict__ Blo_all,
    const float* __restrict__ bias, float* __restrict__ out,
    int K, int mode, int Nrows)
{
    extern __shared__ char smem[];
    uint32_t sb = smem_u32(smem);
    int tid = threadIdx.x;
    int wid = tid >> 5;
    int lane = tid & 31;
    int nbg = blockIdx.y * 128;   // global col base of this block

    int mbase = 0;
    const unsigned short *Bhi, *Blo;
    if (mode == 0) {
        mbase = blockIdx.x * 128;
        Bhi = Bhi_all + (size_t)nbg * K;
        Blo = Blo_all + (size_t)nbg * K;
        if (tid < 128) {
            int grow = mbase + tid;
            if (grow >= Nrows) grow = Nrows - 1;
            ((int*)(smem + SM_SRC))[tid] = grow;
        }
    } else {
        int t = blockIdx.x;
        if (t >= g_ntiles) return;
        int start = g_ts[t], cnt = g_tc[t], rel = g_tr[t];
        Bhi = Bhi_all + ((size_t)rel * 256 + nbg) * K;
        Blo = Blo_all + ((size_t)rel * 256 + nbg) * K;
        if (tid < 128) {
            if (tid < cnt) {
                int e = start + tid;
                int dv = g_dst[e];
                ((int*)(smem + SM_SRC))[tid] = g_src[e];
                ((int*)(smem + SM_DST))[tid] = dv;
                ((float*)(smem + SM_INV))[tid] = g_cnt[dv * RNUM + rel];
            } else {
                ((int*)(smem + SM_SRC))[tid] = g_src[start];
                ((int*)(smem + SM_DST))[tid] = -1;
                ((float*)(smem + SM_INV))[tid] = 0.f;
            }
        }
    }
    __syncthreads();
    const int* s_src = (const int*)(smem + SM_SRC);

    int wm = wid & 3, wn = wid >> 2;
    int a_row = lane & 15;
    int a_k   = (lane >> 4) * 8;
    int b_row = ((lane >> 4) * 8) + (lane & 7);
    int b_k   = ((lane >> 3) & 1) * 8;

    float acc[2][8][4];
#pragma unroll
    for (int i = 0; i < 2; i++)
#pragma unroll
        for (int j = 0; j < 8; j++)
#pragma unroll
            for (int q = 0; q < 4; q++) acc[i][j][q] = 0.f;

    int nst = K >> 5;   // K32 chunks

    // stage issue: 2048 16B segments (4 arrays x 128 rows x 4 segs), 8/thread
    auto issue = [&](int s, int pb) {
        int kb = s << 5;
        uint32_t tb = sb + SM_TILE + pb * BUFB;
#pragma unroll
        for (int u = tid; u < 2048; u += 256) {
            int arr = u >> 9;           // 0 Ahi, 1 Alo, 2 Bhi, 3 Blo
            int v = u & 511;
            int row = v >> 2, seg = v & 3;
            const unsigned short* gp;
            if (arr == 0)      gp = Ahi + (size_t)s_src[row] * K;
            else if (arr == 1) gp = Alo + (size_t)s_src[row] * K;
            else if (arr == 2) gp = Bhi + (size_t)row * K;
            else               gp = Blo + (size_t)row * K;
            cp16(tb + arr * ARRB + row * ROWB + seg * 16, gp + kb + seg * 8);
        }
        asm volatile("cp.async.commit_group;" ::: "memory");
    };

    issue(0, 0);
    for (int s = 0; s < nst; s++) {
        int pb = s & 1;
        if (s + 1 < nst) {
            issue(s + 1, pb ^ 1);
            asm volatile("cp.async.wait_group 1;" ::: "memory");
        } else {
            asm volatile("cp.async.wait_group 0;" ::: "memory");
        }
        __syncthreads();

        uint32_t tb = sb + SM_TILE + pb * BUFB;
#pragma unroll
        for (int ks = 0; ks < 32; ks += 16) {
            uint32_t aH[2][4], aL[2][4];
#pragma unroll
            for (int i = 0; i < 2; i++) {
                uint32_t ra = (32 * wm + 16 * i + a_row) * ROWB + (ks + a_k) * 2;
                ldm_x4(aH[i], tb + 0 * ARRB + ra);
                ldm_x4(aL[i], tb + 1 * ARRB + ra);
            }
#pragma unroll
            for (int p4 = 0; p4 < 4; p4++) {
                uint32_t bh[4], bl[4];
                uint32_t rb = (64 * wn + 16 * p4 + b_row) * ROWB + (ks + b_k) * 2;
                ldm_x4(bh, tb + 2 * ARRB + rb);
                ldm_x4(bl, tb + 3 * ARRB + rb);
#pragma unroll
                for (int i = 0; i < 2; i++) {
#pragma unroll
                    for (int q = 0; q < 2; q++) {
                        float* c = acc[i][2 * p4 + q];
                        mma_bf16(c, aH[i], bh + 2 * q);
                        mma_bf16(c, aH[i], bl + 2 * q);
                        mma_bf16(c, aL[i], bh + 2 * q);
                    }
                }
            }
        }
        __syncthreads();
    }

    // epilogue: lane holds rows {gid, gid+8} of each m16 tile, cols 2*tig,+1 of each n8
    int gid = lane >> 2, tig = lane & 3;
#pragma unroll
    for (int i = 0; i < 2; i++) {
#pragma unroll
        for (int half = 0; half < 2; half++) {
            int m = 32 * wm + 16 * i + gid + 8 * half;
            if (mode == 0) {
                int grow = mbase + m;
                if (grow < Nrows) {
                    float* op = out + (size_t)grow * HDIM + nbg + 64 * wn;
                    const float* bp = bias + nbg + 64 * wn;
#pragma unroll
                    for (int j = 0; j < 8; j++) {
                        int c0 = 8 * j + 2 * tig;
                        op[c0]     = bp[c0]     + acc[i][j][2 * half];
                        op[c0 + 1] = bp[c0 + 1] + acc[i][j][2 * half + 1];
                    }
                }
            } else {
                int dv = ((const int*)(smem + SM_DST))[m];
                float sc = ((const float*)(smem + SM_INV))[m];
                if (dv >= 0) {
                    float* op = out + (size_t)dv * HDIM + nbg + 64 * wn;
#pragma unroll
                    for (int j = 0; j < 8; j++) {
                        int c0 = 8 * j + 2 * tig;
                        red2(&op[c0], sc * acc[i][j][2 * half],
                                      sc * acc[i][j][2 * half + 1]);
                    }
                }
            }
        }
    }
}

// ---------------- pooling (fused ReLU on h2, v2 reductions) ---------------------
// Each lane owns contiguous column pairs: cols {2*(lane+32q), +1}.
__global__ void k_pool(const float* __restrict__ h, const float* __restrict__ wsw,
                       const float* __restrict__ wsb, int N)
{
    int gtid = blockIdx.x * blockDim.x + threadIdx.x;
    int node = gtid >> 5;
    int lane = gtid & 31;
    if (node >= N) return;
    const float2* hr = (const float2*)(h + (size_t)node * HDIM);
    const float2* ws = (const float2*)wsw;
    float2 hv[4];
    float dot = 0.f;
#pragma unroll
    for (int q = 0; q < 4; q++) {
        float2 v = hr[lane + 32 * q];
        v.x = fmaxf(v.x, 0.f);
        v.y = fmaxf(v.y, 0.f);
        hv[q] = v;
        float2 w2 = ws[lane + 32 * q];
        dot += v.x * w2.x + v.y * w2.y;
    }
#pragma unroll
    for (int o = 16; o > 0; o >>= 1) dot += __shfl_xor_sync(0xFFFFFFFFu, dot, o);
    float w = 1.f / (1.f + expf(-(dot + wsb[0])));
    float* er = g_emb + (size_t)g_batch[node] * HDIM;
#pragma unroll
    for (int q = 0; q < 4; q++)
        red2(&er[2 * (lane + 32 * q)], w * hv[q].x, w * hv[q].y);
}

// ---------------- fused MLP head ------------------------------------------------
__global__ void k_mlp(const float* __restrict__ m1w, const float* __restrict__ m1b,
                      const float* __restrict__ m2w, const float* __restrict__ m2b,
                      const float* __restrict__ m3w, const float* __restrict__ m3b,
                      const float* __restrict__ ow,  const float* __restrict__ ob,
                      float* __restrict__ out)
{
    __shared__ float se[HDIM];
    __shared__ float s1[MDIM];
    __shared__ float s2[MDIM];
    __shared__ float sr[MDIM];
    int g = blockIdx.x;
    int t = threadIdx.x;
    for (int k = t; k < HDIM; k += MDIM) se[k] = g_emb[(size_t)g * HDIM + k];
    __syncthreads();
    float a = m1b[t];
    for (int k = 0; k < HDIM; k++) a += se[k] * m1w[k * MDIM + t];
    s1[t] = fmaxf(a, 0.f);
    __syncthreads();
    float b = m2b[t];
    for (int k = 0; k < MDIM; k++) b += s1[k] * m2w[k * MDIM + t];
    s2[t] = fmaxf(b, 0.f);
    __syncthreads();
    float c = m3b[t];
    for (int k = 0; k < MDIM; k++) c += s2[k] * m3w[k * MDIM + t];
    sr[t] = c * ow[t];
    __syncthreads();
    for (int o = 32; o > 0; o >>= 1) {
        if (t < o) sr[t] += sr[t + o];
        __syncthreads();
    }
    if (t == 0) out[g] = sr[0] + ob[0];
}

// ---------------- host side ------------------------------------------------------
extern "C" void kernel_launch(void* const* d_in, const int* in_sizes, int n_in,
                              void* d_out, int out_size)
{
    const float* x     = (const float*)d_in[0];
    const void*  eidx  = d_in[1];
    const void*  ety   = d_in[2];
    const void*  batch = d_in[3];
    const float* W1    = (const float*)d_in[4];
    const float* root1 = (const float*)d_in[5];
    const float* b1    = (const float*)d_in[6];
    const float* W2    = (const float*)d_in[7];
    const float* root2 = (const float*)d_in[8];
    const float* b2    = (const float*)d_in[9];
    const float* wsw   = (const float*)d_in[10];
    const float* wsb   = (const float*)d_in[11];
    const float* m1w   = (const float*)d_in[12];
    const float* m1b   = (const float*)d_in[13];
    const float* m2w   = (const float*)d_in[14];
    const float* m2b   = (const float*)d_in[15];
    const float* m3w   = (const float*)d_in[16];
    const float* m3b   = (const float*)d_in[17];
    const float* ow    = (const float*)d_in[18];
    const float* ob    = (const float*)d_in[19];
    float* out = (float*)d_out;

    int H = in_sizes[6];            // 256
    int F = in_sizes[5] / H;        // 128
    int N = in_sizes[0] / F;        // 50000
    int E = in_sizes[2];            // 200000
    int G = out_size;               // 1600

    float *p_h1, *p_h2;
    unsigned short *p_xhi, *p_xlo, *p_h1hi, *p_h1lo;
    unsigned short *p_w1thi, *p_w1tlo, *p_w2thi, *p_w2tlo;
    unsigned short *p_rt1hi, *p_rt1lo, *p_rt2hi, *p_rt2lo;
    cudaGetSymbolAddress((void**)&p_h1, g_h1);
    cudaGetSymbolAddress((void**)&p_h2, g_h2);
    cudaGetSymbolAddress((void**)&p_xhi, g_xhi);
    cudaGetSymbolAddress((void**)&p_xlo, g_xlo);
    cudaGetSymbolAddress((void**)&p_h1hi, g_h1hi);
    cudaGetSymbolAddress((void**)&p_h1lo, g_h1lo);
    cudaGetSymbolAddress((void**)&p_w1thi, g_w1thi);
    cudaGetSymbolAddress((void**)&p_w1tlo, g_w1tlo);
    cudaGetSymbolAddress((void**)&p_w2thi, g_w2thi);
    cudaGetSymbolAddress((void**)&p_w2tlo, g_w2tlo);
    cudaGetSymbolAddress((void**)&p_rt1hi, g_rt1hi);
    cudaGetSymbolAddress((void**)&p_rt1lo, g_rt1lo);
    cudaGetSymbolAddress((void**)&p_rt2hi, g_rt2hi);
    cudaGetSymbolAddress((void**)&p_rt2lo, g_rt2lo);

    cudaFuncSetAttribute(k_mma, cudaFuncAttributeMaxDynamicSharedMemorySize, SMEM_BYTES);

    int ntilesN = (N + 127) / 128;
    int ubTiles = (E + N + 127) / 128 + RNUM + 1;
    int ncnt = N * RNUM;

    // --- launches 1-3: splits that only need raw inputs ---
    k_split<<<(N * F + 255) / 256, 256>>>(x, p_xhi, p_xlo, N * F, 0);         // 1
    k_split_t<<<(F * H + 255) / 256, 256>>>(root1, p_rt1hi, p_rt1lo, 1, F);   // 2
    k_split_t<<<(H * H + 255) / 256, 256>>>(root2, p_rt2hi, p_rt2lo, 1, H);   // 3

    // --- launch 4 (profiled slot): dense layer-1 GEMM ---
    k_mma<<<dim3(ntilesN, 2), 256, SMEM_BYTES>>>(p_xhi, p_xlo, p_rt1hi, p_rt1lo, b1, p_h1, F, 0, N);  // 4

    // --- index normalization + counts + counting sort by relation ---
    k_detect<<<3, 256>>>(eidx, 2 * E, ety, E, batch, N);
    k_convert_edges<<<(E + 255) / 256, 256>>>(eidx, ety, E);
    k_convert_batch<<<(N + 255) / 256, 256>>>(batch, N);
    k_zero_all<<<(ncnt + 255) / 256, 256>>>(ncnt, G * H);
    k_count<<<(E + N + 255) / 256, 256>>>(E, N);
    k_invert<<<(ncnt + 255) / 256, 256>>>(ncnt);
    k_scan_tiles<<<1, 128>>>(N);
    k_scatter<<<(E + N + 255) / 256, 256>>>(E, N);

    // --- weight splits ---
    k_split_t<<<(RNUM * F * H + 255) / 256, 256>>>(W1, p_w1thi, p_w1tlo, RNUM, F);
    k_split_t<<<(RNUM * H * H + 255) / 256, 256>>>(W2, p_w2thi, p_w2tlo, RNUM, H);

    // --- layer 1 edge aggregation (accumulates onto dense result) ---
    k_mma<<<dim3(ubTiles, 2), 256, SMEM_BYTES>>>(p_xhi, p_xlo, p_w1thi, p_w1tlo, nullptr, p_h1, F, 1, N);

    // --- relu(h1) -> bf16 split ---
    k_split<<<(N * H + 255) / 256, 256>>>(p_h1, p_h1hi, p_h1lo, N * H, 1);

    // --- layer 2: dense + edge ---
    k_mma<<<dim3(ntilesN, 2), 256, SMEM_BYTES>>>(p_h1hi, p_h1lo, p_rt2hi, p_rt2lo, b2, p_h2, H, 0, N);
    k_mma<<<dim3(ubTiles, 2), 256, SMEM_BYTES>>>(p_h1hi, p_h1lo, p_w2thi, p_w2tlo, nullptr, p_h2, H, 1, N);

    // --- weighted-sum pooling (ReLU fused) + MLP head ---
    k_pool<<<(N + 7) / 8, 256>>>(p_h2, wsw, wsb, N);
    k_mlp<<<G, MDIM>>>(m1w, m1b, m2w, m2b, m3w, m3b, ow, ob, out);
}